// round 15
// baseline (speedup 1.0000x reference)
#include <cuda_runtime.h>
#include <cuda_fp16.h>
#include <math.h>
#include <stdint.h>

#define NTOK  8192      // B*S
#define HDIM  1152
#define TOTAL (NTOK*HDIM)
#define SEQ   2048
#define INNERD 4608
#define NMH   4
#define HDH   96
#define MDH   128
#define H4    (HDIM/4)   // 288

// ---------------- scratch (device globals; no allocs allowed) ----------------
__device__ float g_x  [TOTAL];
__device__ float g_a  [TOTAL];
__device__ float g_b  [TOTAL];
__device__ float g_c  [TOTAL];
__device__ float g_q  [NTOK*NMH*HDH];
__device__ float g_k  [NTOK*NMH*HDH];
__device__ float g_v  [NTOK*NMH*MDH];
__device__ float g_g  [NTOK*NMH];
__device__ float g_ga [4*32*NMH];
__device__ float g_gate[NTOK];
__device__ float g_hw [NTOK*12];
// half activation buffers (GEMM A operands)
__device__ __align__(16) __half g_h1 [TOTAL];
__device__ __align__(16) __half g_h2 [TOTAL];
__device__ __align__(16) __half g_gluh[NTOK*INNERD];
__device__ __align__(16) __half g_rh [NTOK*NMH*MDH];
// half weights, [N][K] row-major (GEMM B operands)
__device__ __align__(16) __half g_wp_gp [2304*1152];
__device__ __align__(16) __half g_wp_fi [9216*1152];
__device__ __align__(16) __half g_w_cs [1152*1152];
__device__ __align__(16) __half g_w_mg [1152*1152];
__device__ __align__(16) __half g_w_mx [1152*1152];
__device__ __align__(16) __half g_w_fo [1152*4608];
__device__ __align__(16) __half g_w_mq [4*96*96];
__device__ __align__(16) __half g_w_mk [4*96*96];
__device__ __align__(16) __half g_w_mv [4*128*96];
__device__ __align__(16) __half g_w_mo [4*96*128];
// tap-major conv weights (fp32)
__device__ float g_cs_wt [6*4*1152];
__device__ float g_hd_wt [36*4*96];

__constant__ int c_head_dil[12][3] = {
  {1,2,4},{1,1,1},{4,8,16},{8,16,32},{32,64,128},{64,128,256},
  {256,512,1024},{1,100,200},{1,500,1000},{1,1024,2048},{3,9,27},{5,25,125}
};

__device__ __forceinline__ float sigmoidf_(float x){ return 1.f/(1.f+__expf(-x)); }
__device__ __forceinline__ uint32_t smem_u32(const void* p){
    uint32_t a;
    asm("{ .reg .u64 t; cvta.to.shared.u64 t, %1; cvt.u32.u64 %0, t; }" : "=r"(a) : "l"(p));
    return a;
}
__device__ __forceinline__ void cpasync16(uint32_t s, const void* g){
    asm volatile("cp.async.cg.shared.global [%0], [%1], 16;" :: "r"(s), "l"(g));
}
__device__ __forceinline__ void cpasync16z(uint32_t s, const void* g){
    asm volatile("cp.async.cg.shared.global [%0], [%1], 16, 0;" :: "r"(s), "l"(g));
}
__device__ __forceinline__ void ldsm_x4(uint32_t& r0, uint32_t& r1, uint32_t& r2, uint32_t& r3, uint32_t addr){
    asm volatile("ldmatrix.sync.aligned.m8n8.x4.shared.b16 {%0,%1,%2,%3}, [%4];"
        : "=r"(r0), "=r"(r1), "=r"(r2), "=r"(r3) : "r"(addr));
}
__device__ __forceinline__ void st_h4(__half* p, float a, float b, float c, float d){
    __half2 lo = __floats2half2_rn(a,b);
    __half2 hi = __floats2half2_rn(c,d);
    uint2 u;
    u.x = *(uint32_t*)&lo;
    u.y = *(uint32_t*)&hi;
    *(uint2*)p = u;
}

// ---------------- weight prep: fp32 [z][K][N] -> half [z][N][K] ----------------
template<bool PERM>
__global__ void wtrans_h(const float* __restrict__ in, __half* __restrict__ out, int K, int N)
{
    __shared__ float t[32][33];
    int n0 = blockIdx.x*32, k0 = blockIdx.y*32;
    long zo = (long)blockIdx.z * K * N;
    int tx = threadIdx.x, ty = threadIdx.y;
    int h = N >> 1;
    int n = n0 + tx;
    int col = PERM ? ((n & 1) ? h + (n >> 1) : (n >> 1)) : n;
    #pragma unroll
    for (int j=0;j<32;j+=8)
        t[ty+j][tx] = in[zo + (long)(k0+ty+j)*N + col];
    __syncthreads();
    #pragma unroll
    for (int j=0;j<32;j+=8)
        out[zo + (long)(n0+ty+j)*K + k0+tx] = __float2half_rn(t[tx][ty+j]);
}

// conv weight transpose to tap-major (fp32)
__global__ void wtrans_kernel(const float* __restrict__ cs_w, const float* __restrict__ head_w,
                              float* __restrict__ cs_wt, float* __restrict__ head_wt)
{
    int idx = blockIdx.x*256 + threadIdx.x;
    if (idx < 6*4*1152){
        int i = idx / (4*1152);
        int r = idx % (4*1152);
        int j = r / 1152;
        int c = r % 1152;
        cs_wt[idx] = cs_w[(i*1152 + c)*4 + j];
    }
    if (idx < 36*4*96){
        int hl = idx / (4*96);
        int r  = idx % (4*96);
        int j  = r / 96;
        int c  = r % 96;
        head_wt[idx] = head_w[(hl*96 + c)*4 + j];
    }
}

// ---------------- fused rmsnorm + token scalar gate (fp32 optional + fp16 out) ----------------
__global__ void rms_gate_kernel(const float* __restrict__ x, const float* __restrict__ nw,
                                const float* __restrict__ gw, const float* __restrict__ gb,
                                float* __restrict__ xn, __half* __restrict__ xnh,
                                float* __restrict__ gate)
{
    __shared__ float s1[8], s2[8], sinv;
    int t = blockIdx.x;
    const float4* xr = (const float4*)(x + (long)t*HDIM);
    const float4* gw4 = (const float4*)gw;
    const float4* nw4 = (const float4*)nw;
    float4 vbuf[2];
    float ss=0.f, dg=0.f;
    int nit = 0;
    for (int c=threadIdx.x; c<H4; c+=256){
        float4 v = xr[c]; vbuf[nit++] = v;
        float4 w = gw4[c];
        ss += v.x*v.x + v.y*v.y + v.z*v.z + v.w*v.w;
        dg += v.x*w.x + v.y*w.y + v.z*w.z + v.w*w.w;
    }
    for (int o=16;o;o>>=1){ ss+=__shfl_down_sync(~0u,ss,o); dg+=__shfl_down_sync(~0u,dg,o); }
    int w=threadIdx.x>>5, l=threadIdx.x&31;
    if (l==0){ s1[w]=ss; s2[w]=dg; }
    __syncthreads();
    if (threadIdx.x==0){
        float a=0,bq=0;
        #pragma unroll
        for (int i=0;i<8;i++){ a+=s1[i]; bq+=s2[i]; }
        sinv = rsqrtf(a/(float)HDIM + 1e-6f);
        gate[t] = 1.f/(1.f+expf(-(bq+gb[0])));
    }
    __syncthreads();
    float inv = sinv;
    float4* xo = xn ? (float4*)(xn + (long)t*HDIM) : nullptr;
    __half* xh = xnh + (long)t*HDIM;
    nit = 0;
    for (int c=threadIdx.x; c<H4; c+=256){
        float4 v = vbuf[nit++];
        float4 nwv = nw4[c];
        float o0=v.x*inv*nwv.x, o1=v.y*inv*nwv.y, o2=v.z*inv*nwv.z, o3=v.w*inv*nwv.w;
        if (xo) xo[c] = make_float4(o0,o1,o2,o3);
        st_h4(xh + c*4, o0, o1, o2, o3);
    }
}

// ---------------- conv stack layer (float4, tap-major weights, optional fp16 out) ----------------
__global__ void conv_cs_kernel(const float4* __restrict__ in, float4* __restrict__ out,
                               const float* __restrict__ wt, const float4* __restrict__ bias4,
                               __half* __restrict__ outh, int d, int rnd)
{
    int idx = blockIdx.x*256 + threadIdx.x;
    if (idx >= TOTAL/4) return;
    int c4 = idx % H4;
    int t  = idx / H4;
    int s  = t & (SEQ-1);
    float4 wj[4];
    #pragma unroll
    for (int j=0;j<4;j++) wj[j] = ((const float4*)(wt + j*HDIM))[c4];
    float4 b4 = bias4[c4];
    float acc[4] = {b4.x, b4.y, b4.z, b4.w};
    #pragma unroll
    for (int j=0;j<4;j++){
        int sp = s - (3-j)*d;
        if (sp >= 0){
            float4 xv = in[idx + (sp - s)*H4];
            acc[0] += wj[j].x*xv.x;
            acc[1] += wj[j].y*xv.y;
            acc[2] += wj[j].z*xv.z;
            acc[3] += wj[j].w*xv.w;
        }
    }
    float4 iv = in[idx];
    float4 ov;
    ov.x = iv.x + 0.5f*acc[0]*(1.f + erff(acc[0]*0.70710678118654752f));
    ov.y = iv.y + 0.5f*acc[1]*(1.f + erff(acc[1]*0.70710678118654752f));
    ov.z = iv.z + 0.5f*acc[2]*(1.f + erff(acc[2]*0.70710678118654752f));
    ov.w = iv.w + 0.5f*acc[3]*(1.f + erff(acc[3]*0.70710678118654752f));
    out[idx] = ov;
    if (rnd) st_h4(outh + (long)idx*4, ov.x, ov.y, ov.z, ov.w);
}

// ---------------- head conv layer (float4, tap-major weights) ----------------
__global__ void conv_head_kernel(const float4* __restrict__ in, float4* __restrict__ out,
                                 const float* __restrict__ hwt, const float* __restrict__ hb, int layer)
{
    int idx = blockIdx.x*256 + threadIdx.x;
    if (idx >= TOTAL/4) return;
    int c4 = idx % H4;
    int t  = idx / H4;
    int s  = t & (SEQ-1);
    int ch = c4*4;
    int head = ch / HDH;
    int cin  = ch % HDH;
    int d = c_head_dil[head][layer];
    int hl = head*3 + layer;
    float4 wj[4];
    #pragma unroll
    for (int j=0;j<4;j++) wj[j] = ((const float4*)(hwt + (hl*4 + j)*HDH))[cin>>2];
    float4 b4 = ((const float4*)hb)[(hl*HDH + cin)>>2];
    float acc[4] = {b4.x, b4.y, b4.z, b4.w};
    #pragma unroll
    for (int j=0;j<4;j++){
        int sp = s - (3-j)*d;
        if (sp >= 0){
            float4 xv = in[idx + (sp - s)*H4];
            acc[0] += wj[j].x*xv.x;
            acc[1] += wj[j].y*xv.y;
            acc[2] += wj[j].z*xv.z;
            acc[3] += wj[j].w*xv.w;
        }
    }
    float4 iv = in[idx];
    out[idx] = make_float4(iv.x+acc[0], iv.y+acc[1], iv.z+acc[2], iv.w+acc[3]);
}

// ---------------- hw mul (fp32 inplace + fp16 copy) ----------------
__global__ void hwmul_kernel(float4* __restrict__ a, const float* __restrict__ hw,
                             __half* __restrict__ outh)
{
    int idx = blockIdx.x*256 + threadIdx.x;
    if (idx >= TOTAL/4) return;
    int t = idx / H4, h = (idx % H4)*4/HDH;
    float g = hw[t*12 + h];
    float4 v = a[idx];
    float4 o = make_float4(v.x*g, v.y*g, v.z*g, v.w*g);
    a[idx] = o;
    st_h4(outh + (long)idx*4, o.x, o.y, o.z, o.w);
}

// ---------------- memory-head gate g and chunk means ----------------
__global__ void memg_kernel(const float* __restrict__ xg, const float* __restrict__ gw,
                            const float* __restrict__ gb, float* __restrict__ g)
{
    int t = blockIdx.x;
    int warp = threadIdx.x >> 5, lane = threadIdx.x & 31;
    const float* xr = xg + (long)t*HDIM + (6+warp)*HDH;
    const float* w  = gw + warp*HDH;
    float acc = 0.f;
    for (int c=lane;c<HDH;c+=32) acc += xr[c]*w[c];
    for (int o=16;o;o>>=1) acc += __shfl_down_sync(~0u,acc,o);
    if (lane==0) g[t*NMH+warp] = 1.f/(1.f+expf(-(acc + gb[warp])));
}

__global__ void ga_kernel(const float* __restrict__ g, float* __restrict__ ga)
{
    int e = blockIdx.x*256 + threadIdx.x;
    if (e >= 4*32*NMH) return;
    int n = e % NMH, ch = (e/NMH) % 32, b = e/(NMH*32);
    int base = (b*SEQ + ch*64)*NMH + n;
    float s = 0.f;
    for (int i=0;i<64;i++) s += g[base + i*NMH];
    ga[e] = s*(1.f/64.f);
}

// ---------------- chunked fast-weight scan: grid (16,8), 128 threads ----------------
#define SQS 100
__global__ void scan_kernel(const float* __restrict__ q, const float* __restrict__ kk,
                            const float* __restrict__ v, const float* __restrict__ g,
                            const float* __restrict__ ga, __half* __restrict__ reads)
{
    extern __shared__ float smx[];
    float* sM = smx;               // 96*16
    float* sQ = sM + 96*16;        // 64*SQS
    float* sK = sQ + 64*SQS;       // 64*SQS
    float* sV = sK + 64*SQS;       // 64*16
    float4* sM4 = (float4*)sM;
    float4* sV4 = (float4*)sV;
    int bn = blockIdx.x;
    int b = bn >> 2, n = bn & 3;
    int m0 = blockIdx.y * 16;
    int tid = threadIdx.x;
    const int dd0 = (tid >> 2) * 3;
    const int mg  = tid & 3;

    for (int i=tid;i<96*16;i+=128) sM[i]=0.f;
    __syncthreads();
    for (int ch=0; ch<32; ch++){
        int tok0 = b*SEQ + ch*64;
        #pragma unroll
        for (int it=0; it<12; it++){
            int i = tid + it*128;
            int s = i/24, cc = i%24;
            long base = (long)(tok0+s)*(NMH*HDH) + n*HDH;
            float gv = g[(tok0+s)*NMH + n];
            float4 qv = ((const float4*)(q + base))[cc];
            float4 kv = ((const float4*)(kk + base))[cc];
            ((float4*)(sQ + s*SQS))[cc] = qv;
            ((float4*)(sK + s*SQS))[cc] = make_float4(kv.x*gv, kv.y*gv, kv.z*gv, kv.w*gv);
        }
        #pragma unroll
        for (int it=0; it<2; it++){
            int i = tid + it*128;
            int s = i >> 2, mm = i & 3;
            sV4[i] = ((const float4*)(v + (long)(tok0+s)*(NMH*MDH) + n*MDH + m0))[mm];
        }
        __syncthreads();
        #pragma unroll
        for (int it=0; it<2; it++){
            int item = tid + it*128;
            int s = item >> 2, mgg = item & 3;
            const float* qs = sQ + s*SQS;
            float4 acc = make_float4(0.f,0.f,0.f,0.f);
            #pragma unroll 4
            for (int dd=0; dd<96; dd++){
                float qv = qs[dd];
                float4 mv = sM4[dd*4 + mgg];
                acc.x += qv*mv.x; acc.y += qv*mv.y; acc.z += qv*mv.z; acc.w += qv*mv.w;
            }
            st_h4(reads + (long)(tok0+s)*(NMH*MDH) + n*MDH + m0 + mgg*4,
                  acc.x, acc.y, acc.z, acc.w);
        }
        __syncthreads();
        float gav = ga[(b*32+ch)*NMH + n];
        float om = 1.f - gav;
        float4 a0 = sM4[(dd0+0)*4+mg];
        float4 a1 = sM4[(dd0+1)*4+mg];
        float4 a2 = sM4[(dd0+2)*4+mg];
        a0.x*=om; a0.y*=om; a0.z*=om; a0.w*=om;
        a1.x*=om; a1.y*=om; a1.z*=om; a1.w*=om;
        a2.x*=om; a2.y*=om; a2.z*=om; a2.w*=om;
        __syncthreads();
        #pragma unroll 2
        for (int s=0;s<64;s++){
            const float* ks = sK + s*SQS + dd0;
            float k0 = ks[0], k1 = ks[1], k2 = ks[2];
            float4 vv = sV4[s*4+mg];
            a0.x += k0*vv.x; a0.y += k0*vv.y; a0.z += k0*vv.z; a0.w += k0*vv.w;
            a1.x += k1*vv.x; a1.y += k1*vv.y; a1.z += k1*vv.z; a1.w += k1*vv.w;
            a2.x += k2*vv.x; a2.y += k2*vv.y; a2.z += k2*vv.z; a2.w += k2*vv.w;
        }
        sM4[(dd0+0)*4+mg] = a0;
        sM4[(dd0+1)*4+mg] = a1;
        sM4[(dd0+2)*4+mg] = a2;
        __syncthreads();
    }
}
#define SCAN_SMEM ((96*16 + 2*64*SQS + 64*16)*4)   // 59392

// ---------------- SIMT fp32 GEMM (router, N=12) ----------------
template<bool BIAS, bool ACC, int ACT>
__global__ __launch_bounds__(256) void sgemm(
    const float* __restrict__ A, const float* __restrict__ B,
    const float* __restrict__ bias, float* __restrict__ C,
    int M, int N, int K, int lda, int ldb, int ldc,
    long sA, long sB, long sC)
{
    __shared__ __align__(16) float As[8*128];
    __shared__ __align__(16) float Bs[8*128];
    A += (long)blockIdx.z * sA;
    B += (long)blockIdx.z * sB;
    C += (long)blockIdx.z * sC;
    int tid = threadIdx.x;
    int row0 = blockIdx.y * 128;
    int col0 = blockIdx.x * 128;
    int tr4 = (tid >> 4) * 4;
    int tc4 = (tid & 15) * 4;
    int arow = tid >> 1, acol = (tid & 1) * 4;
    int brow = tid >> 5, bcol = (tid & 31) * 4;
    const float* Aptr = A + (long)(row0 + arow)*lda + acol;
    const float* Bptr = B + (long)brow*ldb + col0 + bcol;
    bool bvalid = (col0 + bcol + 3) < N;
    float acc[8][8];
    #pragma unroll
    for (int i=0;i<8;i++)
        #pragma unroll
        for (int j=0;j<8;j++) acc[i][j]=0.f;

    for (int k0=0;k0<K;k0+=8){
        float4 av = *(const float4*)Aptr;
        As[(acol+0)*128 + arow]=av.x;
        As[(acol+1)*128 + arow]=av.y;
        As[(acol+2)*128 + arow]=av.z;
        As[(acol+3)*128 + arow]=av.w;
        float4 bv = bvalid ? *(const float4*)Bptr : make_float4(0.f,0.f,0.f,0.f);
        *(float4*)&Bs[brow*128 + bcol] = bv;
        __syncthreads();
        #pragma unroll
        for (int k=0;k<8;k++){
            float4 a0 = *(const float4*)&As[k*128 + tr4];
            float4 a1 = *(const float4*)&As[k*128 + tr4 + 64];
            float4 b0 = *(const float4*)&Bs[k*128 + tc4];
            float4 b1 = *(const float4*)&Bs[k*128 + tc4 + 64];
            float ra[8] = {a0.x,a0.y,a0.z,a0.w,a1.x,a1.y,a1.z,a1.w};
            float rb[8] = {b0.x,b0.y,b0.z,b0.w,b1.x,b1.y,b1.z,b1.w};
            #pragma unroll
            for (int i=0;i<8;i++)
                #pragma unroll
                for (int j=0;j<8;j++) acc[i][j] += ra[i]*rb[j];
        }
        __syncthreads();
        Aptr += 8;
        Bptr += 8*(long)ldb;
    }
    #pragma unroll
    for (int i=0;i<8;i++){
        int r = row0 + tr4 + (i<4 ? i : i-4+64);
        #pragma unroll
        for (int j=0;j<8;j++){
            int cN = col0 + tc4 + (j<4 ? j : j-4+64);
            if (cN < N){
                float v = acc[i][j];
                if (BIAS) v += bias[cN];
                if (ACC)  v += C[(long)r*ldc + cN];
                if (ACT==1) v = 1.f/(1.f+expf(-v));
                C[(long)r*ldc + cN] = v;
            }
        }
    }
}

// ---------------- fp16 tensor-core GEMM (m16n8k16, ldmatrix, cp.async 3-stage) ----------------
// C[M,N] = A[M,K](half, row-major) @ B[N,K](half, row-major)^T, fp32 accumulate. ldb = K-stride.
// EPI: 0 plain(+bias), 1 resid Cf=E+gate[r]*(acc+bias), 2 mulsig out=E*sig(acc+bias),
//      3 Cf+=acc, 4 GLU pairs out[r][cN/2]=acc_even*sig(acc_odd) (ldc=N/2)
// OM: 0 = fp32 out only (Cf), 1 = half out only (Ch), 2 = both.
#define ASTH 24
#define BSTH 24
#define SFTH (128*ASTH + 128*BSTH)   // 6144 halves per stage
template<bool BIAS, int EPI, int OM>
__global__ __launch_bounds__(256) void hgemm(
    const __half* __restrict__ A, const __half* __restrict__ B,
    const float* __restrict__ bias, float* __restrict__ Cf, __half* __restrict__ Ch,
    const float* __restrict__ E, const float* __restrict__ gate,
    int M, int N, int K, int lda, int ldb, int ldc,
    long zA, long zB, long zC)
{
    __shared__ __align__(16) __half smh[3*SFTH];

    A += (long)blockIdx.z * zA;
    B += (long)blockIdx.z * zB;
    if (OM != 1) Cf += (long)blockIdx.z * zC;
    if (OM != 0) Ch += (long)blockIdx.z * zC;
    if (EPI == 1 || EPI == 2) E += (long)blockIdx.z * zC;

    const int tid  = threadIdx.x;
    const int lane = tid & 31;
    const int wid  = tid >> 5;
    const int wm   = (wid >> 2) * 64;
    const int wn   = (wid & 3) * 32;
    const int qr   = lane >> 2;
    const int qc   = lane & 3;

    const int row0 = blockIdx.y * 128;
    const int col0 = blockIdx.x * 128;

    const int lr   = tid >> 1;
    const int lsg  = (tid & 1) * 8;
    const bool bok = (col0 + lr) < N;

    // ldmatrix per-thread source rows (in halves)
    const int a_row  = wm + (lane & 15);          // + i*16
    const int a_koff = (lane >> 4) * 8;
    const int b_row  = wn + (lane & 7) + ((lane & 16) ? 8 : 0);   // + j2*16
    const int b_koff = (lane & 8) ? 8 : 0;

    float acc[4][4][4];
    #pragma unroll
    for (int i=0;i<4;i++)
        #pragma unroll
        for (int j=0;j<4;j++)
            #pragma unroll
            for (int e=0;e<4;e++) acc[i][j][e]=0.f;

    const int nt = K >> 4;

    auto issue = [&](int t){
        __half* as = smh + (t%3)*SFTH;
        __half* bs = as + 128*ASTH;
        const int kb = t*16;
        cpasync16(smem_u32(as + lr*ASTH + lsg), A + (long)(row0 + lr)*lda + kb + lsg);
        if (bok)
            cpasync16(smem_u32(bs + lr*BSTH + lsg), B + (long)(col0 + lr)*ldb + kb + lsg);
        else
            cpasync16z(smem_u32(bs + lr*BSTH + lsg), B);
        asm volatile("cp.async.commit_group;" ::: "memory");
    };

    issue(0);
    if (nt > 1) issue(1);

    for (int t=0; t<nt; t++){
        if (t+1 < nt) asm volatile("cp.async.wait_group 1;" ::: "memory");
        else          asm volatile("cp.async.wait_group 0;" ::: "memory");
        __syncthreads();
        if (t+2 < nt) issue(t+2);
        const __half* as = smh + (t%3)*SFTH;
        const __half* bs = as + 128*ASTH;
        uint32_t abase = smem_u32(as + a_row*ASTH + a_koff);
        uint32_t bbase = smem_u32(bs + b_row*BSTH + b_koff);
        uint32_t af[4][4], bf[4][2];
        #pragma unroll
        for (int i=0;i<4;i++)
            ldsm_x4(af[i][0], af[i][1], af[i][2], af[i][3], abase + i*16*ASTH*2);
        #pragma unroll
        for (int j2=0;j2<2;j2++)
            ldsm_x4(bf[2*j2][0], bf[2*j2][1], bf[2*j2+1][0], bf[2*j2+1][1], bbase + j2*16*BSTH*2);
        #pragma unroll
        for (int i=0;i<4;i++)
            #pragma unroll
            for (int j=0;j<4;j++){
                asm volatile(
                    "mma.sync.aligned.m16n8k16.row.col.f32.f16.f16.f32 "
                    "{%0,%1,%2,%3},{%4,%5,%6,%7},{%8,%9},{%0,%1,%2,%3};"
                    : "+f"(acc[i][j][0]), "+f"(acc[i][j][1]),
                      "+f"(acc[i][j][2]), "+f"(acc[i][j][3])
                    : "r"(af[i][0]), "r"(af[i][1]), "r"(af[i][2]), "r"(af[i][3]),
                      "r"(bf[j][0]), "r"(bf[j][1]));
            }
    }

    // epilogue
    #pragma unroll
    for (int i=0;i<4;i++){
        int r0 = row0 + wm + i*16 + qr;
        float gg0 = 0.f, gg1 = 0.f;
        if (EPI == 1){ gg0 = gate[r0]; gg1 = gate[r0+8]; }
        #pragma unroll
        for (int j=0;j<4;j++){
            int cN = col0 + wn + j*8 + qc*2;
            if (cN < N){
                float bv0 = BIAS ? bias[cN]   : 0.f;
                float bv1 = BIAS ? bias[cN+1] : 0.f;
                float v0 = acc[i][j][0] + bv0;
                float v1 = acc[i][j][1] + bv1;
                float v2 = acc[i][j][2] + bv0;
                float v3 = acc[i][j][3] + bv1;
                if (EPI == 4){
                    long p0 = (long)r0*ldc + (cN>>1);
                    long p1 = (long)(r0+8)*ldc + (cN>>1);
                    float g0 = v0*sigmoidf_(v1);
                    float g1 = v2*sigmoidf_(v3);
                    if (OM != 1){ Cf[p0] = g0; Cf[p1] = g1; }
                    if (OM != 0){ Ch[p0] = __float2half_rn(g0); Ch[p1] = __float2half_rn(g1); }
                } else {
                    long o00 = (long)r0*ldc + cN;
                    long o10 = (long)(r0+8)*ldc + cN;
                    if (EPI == 1){
                        v0 = E[o00]   + gg0*v0;
                        v1 = E[o00+1] + gg0*v1;
                        v2 = E[o10]   + gg1*v2;
                        v3 = E[o10+1] + gg1*v3;
                    } else if (EPI == 2){
                        v0 = E[o00]  *sigmoidf_(v0);
                        v1 = E[o00+1]*sigmoidf_(v1);
                        v2 = E[o10]  *sigmoidf_(v2);
                        v3 = E[o10+1]*sigmoidf_(v3);
                    } else if (EPI == 3){
                        v0 += Cf[o00]; v1 += Cf[o00+1]; v2 += Cf[o10]; v3 += Cf[o10+1];
                    }
                    if (OM != 1){
                        Cf[o00] = v0; Cf[o00+1] = v1;
                        Cf[o10] = v2; Cf[o10+1] = v3;
                    }
                    if (OM != 0){
                        __half2 h0 = __floats2half2_rn(v0, v1);
                        __half2 h1 = __floats2half2_rn(v2, v3);
                        *(__half2*)(Ch + o00) = h0;
                        *(__half2*)(Ch + o10) = h1;
                    }
                }
            }
        }
    }
}

// ---------------- host ----------------
extern "C" void kernel_launch(void* const* d_in, const int* in_sizes, int n_in,
                              void* d_out, int out_size)
{
    const float* x          = (const float*)d_in[0];
    const float* norm1_w    = (const float*)d_in[1];
    const float* norm2_w    = (const float*)d_in[2];
    const float* norm3_w    = (const float*)d_in[3];
    const float* cs_w       = (const float*)d_in[4];
    const float* cs_b       = (const float*)d_in[5];
    const float* cs_proj_w  = (const float*)d_in[6];
    const float* cs_proj_b  = (const float*)d_in[7];
    const float* gate_proj_w= (const float*)d_in[8];
    const float* router_w   = (const float*)d_in[9];
    const float* router_b   = (const float*)d_in[10];
    const float* head_w     = (const float*)d_in[11];
    const float* head_b     = (const float*)d_in[12];
    const float* mem_q      = (const float*)d_in[13];
    const float* mem_k      = (const float*)d_in[14];
    const float* mem_v      = (const float*)d_in[15];
    const float* mem_gw     = (const float*)d_in[16];
    const float* mem_gb     = (const float*)d_in[17];
    const float* mem_out    = (const float*)d_in[18];
    const float* mixgate_w  = (const float*)d_in[19];
    const float* mixgate_b  = (const float*)d_in[20];
    const float* mixing_w   = (const float*)d_in[21];
    const float* mixing_b   = (const float*)d_in[22];
    const float* ffn_in_w   = (const float*)d_in[23];
    const float* ffn_out_w  = (const float*)d_in[24];
    const float* cg_w       = (const float*)d_in[25];
    const float* cg_b       = (const float*)d_in[26];
    const float* sg_w       = (const float*)d_in[27];
    const float* sg_b       = (const float*)d_in[28];
    const float* fg_w       = (const float*)d_in[29];
    const float* fg_b       = (const float*)d_in[30];

    float *X,*A,*Bb,*C,*Q,*Kb,*V,*G,*GA,*GATE,*HW,*CSWT,*HDWT;
    __half *H1,*H2,*GLUH,*RH,*WPGP,*WPFI,*WCS,*WMG,*WMX,*WFO,*WMQ,*WMK,*WMV,*WMO;
    cudaGetSymbolAddress((void**)&X,  g_x);
    cudaGetSymbolAddress((void**)&A,  g_a);
    cudaGetSymbolAddress((void**)&Bb, g_b);
    cudaGetSymbolAddress((void**)&C,  g_c);
    cudaGetSymbolAddress((void**)&Q,  g_q);
    cudaGetSymbolAddress((void**)&Kb, g_k);
    cudaGetSymbolAddress((void**)&V,  g_v);
    cudaGetSymbolAddress((void**)&G,  g_g);
    cudaGetSymbolAddress((void**)&GA, g_ga);
    cudaGetSymbolAddress((void**)&GATE,g_gate);
    cudaGetSymbolAddress((void**)&HW, g_hw);
    cudaGetSymbolAddress((void**)&CSWT, g_cs_wt);
    cudaGetSymbolAddress((void**)&HDWT, g_hd_wt);
    cudaGetSymbolAddress((void**)&H1, g_h1);
    cudaGetSymbolAddress((void**)&H2, g_h2);
    cudaGetSymbolAddress((void**)&GLUH, g_gluh);
    cudaGetSymbolAddress((void**)&RH, g_rh);
    cudaGetSymbolAddress((void**)&WPGP, g_wp_gp);
    cudaGetSymbolAddress((void**)&WPFI, g_wp_fi);
    cudaGetSymbolAddress((void**)&WCS, g_w_cs);
    cudaGetSymbolAddress((void**)&WMG, g_w_mg);
    cudaGetSymbolAddress((void**)&WMX, g_w_mx);
    cudaGetSymbolAddress((void**)&WFO, g_w_fo);
    cudaGetSymbolAddress((void**)&WMQ, g_w_mq);
    cudaGetSymbolAddress((void**)&WMK, g_w_mk);
    cudaGetSymbolAddress((void**)&WMV, g_w_mv);
    cudaGetSymbolAddress((void**)&WMO, g_w_mo);

    cudaFuncSetAttribute(scan_kernel, cudaFuncAttributeMaxDynamicSharedMemorySize, SCAN_SMEM);

    const int EB4 = TOTAL/4/256;   // 9216
    dim3 tb(32,8);

    // ===== weight preps: half [N][K] transposed (+pair-interleave for GLU) =====
    wtrans_h<true> <<<dim3(72,36,1),  tb>>>(gate_proj_w, WPGP, 1152, 2304);
    wtrans_h<true> <<<dim3(288,36,1), tb>>>(ffn_in_w,    WPFI, 1152, 9216);
    wtrans_h<false><<<dim3(36,36,1),  tb>>>(cs_proj_w,   WCS,  1152, 1152);
    wtrans_h<false><<<dim3(36,36,1),  tb>>>(mixgate_w,   WMG,  1152, 1152);
    wtrans_h<false><<<dim3(36,36,1),  tb>>>(mixing_w,    WMX,  1152, 1152);
    wtrans_h<false><<<dim3(36,144,1), tb>>>(ffn_out_w,   WFO,  4608, 1152);
    wtrans_h<false><<<dim3(3,3,4),    tb>>>(mem_q,       WMQ,  96, 96);
    wtrans_h<false><<<dim3(3,3,4),    tb>>>(mem_k,       WMK,  96, 96);
    wtrans_h<false><<<dim3(4,3,4),    tb>>>(mem_v,       WMV,  96, 128);
    wtrans_h<false><<<dim3(3,4,4),    tb>>>(mem_out,     WMO,  128, 96);
    wtrans_kernel<<<108,256>>>(cs_w, head_w, CSWT, HDWT);

    // ===== stage 1: conv stack =====
    rms_gate_kernel<<<NTOK,256>>>(x, norm1_w, cg_w, cg_b, A, H1, GATE);
    {
        const int dil[6] = {1,2,4,8,16,32};
        float* pin = A; float* pout = Bb;
        for (int i=0;i<6;i++){
            conv_cs_kernel<<<EB4,256>>>((const float4*)pin, (float4*)pout,
                CSWT + i*4*HDIM, (const float4*)(cs_b + i*HDIM), H1, dil[i], i==5);
            float* tmp = pin; pin = pout; pout = tmp;
        }
    }
    // X = x + gate*(H1@cs_proj + b)
    hgemm<true,1,0><<<dim3(9,64,1),256>>>(H1, WCS, cs_proj_b, X, nullptr, x, GATE,
        NTOK, HDIM, HDIM, HDIM, HDIM, HDIM, 0,0,0);

    // ===== stage 2: multi-head state =====
    rms_gate_kernel<<<NTOK,256>>>(X, norm2_w, sg_w, sg_b, A, H1, GATE);
    sgemm<true,false,1><<<dim3(1,64,1),256>>>(A, router_w, router_b, HW,
        NTOK, 12, HDIM, HDIM, 12, 12, 0,0,0);
    // Bb(f32) + H2(h16) = glu(H1 @ gate_proj)
    hgemm<false,4,2><<<dim3(18,64,1),256>>>(H1, WPGP, nullptr, Bb, H2, nullptr, nullptr,
        NTOK, 2304, HDIM, HDIM, HDIM, HDIM, 0,0,0);
    memg_kernel<<<NTOK,128>>>(Bb, mem_gw, mem_gb, G);
    ga_kernel<<<2,256>>>(G, GA);
    hgemm<false,0,0><<<dim3(1,64,4),256>>>(H2 + 6*HDH, WMQ, nullptr, Q, nullptr, nullptr, nullptr,
        NTOK, HDH, HDH, HDIM, HDH, NMH*HDH, HDH, HDH*HDH, HDH);
    hgemm<false,0,0><<<dim3(1,64,4),256>>>(H2 + 6*HDH, WMK, nullptr, Kb, nullptr, nullptr, nullptr,
        NTOK, HDH, HDH, HDIM, HDH, NMH*HDH, HDH, HDH*HDH, HDH);
    hgemm<false,0,0><<<dim3(1,64,4),256>>>(H2 + 6*HDH, WMV, nullptr, V, nullptr, nullptr, nullptr,
        NTOK, MDH, HDH, HDIM, HDH, NMH*MDH, HDH, HDH*MDH, MDH);
    conv_head_kernel<<<EB4,256>>>((const float4*)Bb, (float4*)C, HDWT, head_b, 0);
    conv_head_kernel<<<EB4,256>>>((const float4*)C,  (float4*)A, HDWT, head_b, 1);
    conv_head_kernel<<<EB4,256>>>((const float4*)A,  (float4*)C, HDWT, head_b, 2);
    scan_kernel<<<dim3(16,8),128,SCAN_SMEM>>>(Q, Kb, V, G, GA, RH);
    // C[:, memheads] += RH @ mem_out
    hgemm<false,3,0><<<dim3(1,64,4),256>>>(RH, WMO, nullptr, C + 6*HDH, nullptr, nullptr, nullptr,
        NTOK, HDH, MDH, NMH*MDH, MDH, HDIM, MDH, MDH*HDH, HDH);
    hwmul_kernel<<<EB4,256>>>((float4*)C, HW, H1);
    // H2 = C * sigmoid(H1@mixgate + b)
    hgemm<true,2,1><<<dim3(9,64,1),256>>>(H1, WMG, mixgate_b, nullptr, H2, C, nullptr,
        NTOK, HDIM, HDIM, HDIM, HDIM, HDIM, 0,0,0);
    // X = X + gate*(H2@mixing + b)
    hgemm<true,1,0><<<dim3(9,64,1),256>>>(H2, WMX, mixing_b, X, nullptr, X, GATE,
        NTOK, HDIM, HDIM, HDIM, HDIM, HDIM, 0,0,0);

    // ===== stage 3: GLU FFN =====
    rms_gate_kernel<<<NTOK,256>>>(X, norm3_w, fg_w, fg_b, nullptr, H1, GATE);
    // GLUH = glu(H1 @ ffn_in)
    hgemm<false,4,1><<<dim3(72,64,1),256>>>(H1, WPFI, nullptr, nullptr, GLUH, nullptr, nullptr,
        NTOK, 9216, HDIM, HDIM, HDIM, INNERD, 0,0,0);
    // out = X + gate*(GLUH@ffn_out)
    hgemm<false,1,0><<<dim3(9,64,1),256>>>(GLUH, WFO, nullptr, (float*)d_out, nullptr, X, GATE,
        NTOK, HDIM, INNERD, INNERD, INNERD, HDIM, 0,0,0);

    (void)in_sizes; (void)n_in; (void)out_size;
}

// round 16
// speedup vs baseline: 1.2810x; 1.2810x over previous
#include <cuda_runtime.h>
#include <cuda_fp16.h>
#include <math.h>
#include <stdint.h>

#define NTOK  8192      // B*S
#define HDIM  1152
#define TOTAL (NTOK*HDIM)
#define SEQ   2048
#define INNERD 4608
#define NMH   4
#define HDH   96
#define MDH   128
#define H4    (HDIM/4)   // 288

// ---------------- scratch (device globals; no allocs allowed) ----------------
__device__ float g_x  [TOTAL];
__device__ float g_a  [TOTAL];
__device__ float g_b  [TOTAL];
__device__ float g_c  [TOTAL];
__device__ float g_q  [NTOK*NMH*HDH];
__device__ float g_k  [NTOK*NMH*HDH];
__device__ float g_v  [NTOK*NMH*MDH];
__device__ float g_g  [NTOK*NMH];
__device__ float g_ga [4*32*NMH];
__device__ float g_gate[NTOK];
__device__ float g_hw [NTOK*12];
// half activation buffers (GEMM A operands)
__device__ __align__(16) __half g_h1 [TOTAL];
__device__ __align__(16) __half g_h2 [TOTAL];
__device__ __align__(16) __half g_gluh[NTOK*INNERD];
__device__ __align__(16) __half g_rh [NTOK*NMH*MDH];
// half weights, [N][K] row-major (GEMM B operands)
__device__ __align__(16) __half g_wp_gp [2304*1152];
__device__ __align__(16) __half g_wp_fi [9216*1152];
__device__ __align__(16) __half g_w_cs [1152*1152];
__device__ __align__(16) __half g_w_mg [1152*1152];
__device__ __align__(16) __half g_w_mx [1152*1152];
__device__ __align__(16) __half g_w_fo [1152*4608];
__device__ __align__(16) __half g_w_mq [4*96*96];
__device__ __align__(16) __half g_w_mk [4*96*96];
__device__ __align__(16) __half g_w_mv [4*128*96];
__device__ __align__(16) __half g_w_mo [4*96*128];
// tap-major conv weights (fp32)
__device__ float g_cs_wt [6*4*1152];
__device__ float g_hd_wt [36*4*96];

__constant__ int c_head_dil[12][3] = {
  {1,2,4},{1,1,1},{4,8,16},{8,16,32},{32,64,128},{64,128,256},
  {256,512,1024},{1,100,200},{1,500,1000},{1,1024,2048},{3,9,27},{5,25,125}
};

__device__ __forceinline__ float sigmoidf_(float x){ return 1.f/(1.f+__expf(-x)); }
__device__ __forceinline__ uint32_t smem_u32(const void* p){
    uint32_t a;
    asm("{ .reg .u64 t; cvta.to.shared.u64 t, %1; cvt.u32.u64 %0, t; }" : "=r"(a) : "l"(p));
    return a;
}
__device__ __forceinline__ void cpasync16(uint32_t s, const void* g){
    asm volatile("cp.async.cg.shared.global [%0], [%1], 16;" :: "r"(s), "l"(g));
}
__device__ __forceinline__ void cpasync16z(uint32_t s, const void* g){
    asm volatile("cp.async.cg.shared.global [%0], [%1], 16, 0;" :: "r"(s), "l"(g));
}
__device__ __forceinline__ void st_h4(__half* p, float a, float b, float c, float d){
    __half2 lo = __floats2half2_rn(a,b);
    __half2 hi = __floats2half2_rn(c,d);
    uint2 u;
    u.x = *(uint32_t*)&lo;
    u.y = *(uint32_t*)&hi;
    *(uint2*)p = u;
}

// ---------------- weight prep: fp32 [z][K][N] -> half [z][N][K] ----------------
template<bool PERM>
__global__ void wtrans_h(const float* __restrict__ in, __half* __restrict__ out, int K, int N)
{
    __shared__ float t[32][33];
    int n0 = blockIdx.x*32, k0 = blockIdx.y*32;
    long zo = (long)blockIdx.z * K * N;
    int tx = threadIdx.x, ty = threadIdx.y;
    int h = N >> 1;
    int n = n0 + tx;
    int col = PERM ? ((n & 1) ? h + (n >> 1) : (n >> 1)) : n;
    #pragma unroll
    for (int j=0;j<32;j+=8)
        t[ty+j][tx] = in[zo + (long)(k0+ty+j)*N + col];
    __syncthreads();
    #pragma unroll
    for (int j=0;j<32;j+=8)
        out[zo + (long)(n0+ty+j)*K + k0+tx] = __float2half_rn(t[tx][ty+j]);
}

// conv weight transpose to tap-major (fp32)
__global__ void wtrans_kernel(const float* __restrict__ cs_w, const float* __restrict__ head_w,
                              float* __restrict__ cs_wt, float* __restrict__ head_wt)
{
    int idx = blockIdx.x*256 + threadIdx.x;
    if (idx < 6*4*1152){
        int i = idx / (4*1152);
        int r = idx % (4*1152);
        int j = r / 1152;
        int c = r % 1152;
        cs_wt[idx] = cs_w[(i*1152 + c)*4 + j];
    }
    if (idx < 36*4*96){
        int hl = idx / (4*96);
        int r  = idx % (4*96);
        int j  = r / 96;
        int c  = r % 96;
        head_wt[idx] = head_w[(hl*96 + c)*4 + j];
    }
}

// ---------------- fused rmsnorm + token scalar gate (fp32 optional + fp16 out) ----------------
__global__ void rms_gate_kernel(const float* __restrict__ x, const float* __restrict__ nw,
                                const float* __restrict__ gw, const float* __restrict__ gb,
                                float* __restrict__ xn, __half* __restrict__ xnh,
                                float* __restrict__ gate)
{
    __shared__ float s1[8], s2[8], sinv;
    int t = blockIdx.x;
    const float4* xr = (const float4*)(x + (long)t*HDIM);
    const float4* gw4 = (const float4*)gw;
    const float4* nw4 = (const float4*)nw;
    float4 vbuf[2];
    float ss=0.f, dg=0.f;
    int nit = 0;
    for (int c=threadIdx.x; c<H4; c+=256){
        float4 v = xr[c]; vbuf[nit++] = v;
        float4 w = gw4[c];
        ss += v.x*v.x + v.y*v.y + v.z*v.z + v.w*v.w;
        dg += v.x*w.x + v.y*w.y + v.z*w.z + v.w*w.w;
    }
    for (int o=16;o;o>>=1){ ss+=__shfl_down_sync(~0u,ss,o); dg+=__shfl_down_sync(~0u,dg,o); }
    int w=threadIdx.x>>5, l=threadIdx.x&31;
    if (l==0){ s1[w]=ss; s2[w]=dg; }
    __syncthreads();
    if (threadIdx.x==0){
        float a=0,bq=0;
        #pragma unroll
        for (int i=0;i<8;i++){ a+=s1[i]; bq+=s2[i]; }
        sinv = rsqrtf(a/(float)HDIM + 1e-6f);
        gate[t] = 1.f/(1.f+expf(-(bq+gb[0])));
    }
    __syncthreads();
    float inv = sinv;
    float4* xo = xn ? (float4*)(xn + (long)t*HDIM) : nullptr;
    __half* xh = xnh + (long)t*HDIM;
    nit = 0;
    for (int c=threadIdx.x; c<H4; c+=256){
        float4 v = vbuf[nit++];
        float4 nwv = nw4[c];
        float o0=v.x*inv*nwv.x, o1=v.y*inv*nwv.y, o2=v.z*inv*nwv.z, o3=v.w*inv*nwv.w;
        if (xo) xo[c] = make_float4(o0,o1,o2,o3);
        st_h4(xh + c*4, o0, o1, o2, o3);
    }
}

// ---------------- router from fp16 normed input: hw = sigmoid(xh @ rw + rb) ----------------
__global__ void router_kernel(const __half* __restrict__ xh, const float* __restrict__ rw,
                              const float* __restrict__ rb, float* __restrict__ hw)
{
    __shared__ float xs[HDIM];
    int t = blockIdx.x;
    const __half* xr = xh + (long)t*HDIM;
    for (int c=threadIdx.x; c<HDIM; c+=128) xs[c] = __half2float(xr[c]);
    __syncthreads();
    int w = threadIdx.x >> 5, l = threadIdx.x & 31;
    for (int o=w; o<12; o+=4){
        float acc = 0.f;
        for (int c=l; c<HDIM; c+=32) acc += xs[c]*rw[c*12 + o];
        for (int off=16; off; off>>=1) acc += __shfl_down_sync(~0u, acc, off);
        if (l==0) hw[t*12 + o] = 1.f/(1.f+expf(-(acc + rb[o])));
    }
}

// ---------------- conv stack layer (float4, tap-major weights, optional fp16 out) ----------------
__global__ void conv_cs_kernel(const float4* __restrict__ in, float4* __restrict__ out,
                               const float* __restrict__ wt, const float4* __restrict__ bias4,
                               __half* __restrict__ outh, int d, int rnd)
{
    int idx = blockIdx.x*256 + threadIdx.x;
    if (idx >= TOTAL/4) return;
    int c4 = idx % H4;
    int t  = idx / H4;
    int s  = t & (SEQ-1);
    float4 wj[4];
    #pragma unroll
    for (int j=0;j<4;j++) wj[j] = ((const float4*)(wt + j*HDIM))[c4];
    float4 b4 = bias4[c4];
    float acc[4] = {b4.x, b4.y, b4.z, b4.w};
    #pragma unroll
    for (int j=0;j<4;j++){
        int sp = s - (3-j)*d;
        if (sp >= 0){
            float4 xv = in[idx + (sp - s)*H4];
            acc[0] += wj[j].x*xv.x;
            acc[1] += wj[j].y*xv.y;
            acc[2] += wj[j].z*xv.z;
            acc[3] += wj[j].w*xv.w;
        }
    }
    float4 iv = in[idx];
    float4 ov;
    ov.x = iv.x + 0.5f*acc[0]*(1.f + erff(acc[0]*0.70710678118654752f));
    ov.y = iv.y + 0.5f*acc[1]*(1.f + erff(acc[1]*0.70710678118654752f));
    ov.z = iv.z + 0.5f*acc[2]*(1.f + erff(acc[2]*0.70710678118654752f));
    ov.w = iv.w + 0.5f*acc[3]*(1.f + erff(acc[3]*0.70710678118654752f));
    out[idx] = ov;
    if (rnd) st_h4(outh + (long)idx*4, ov.x, ov.y, ov.z, ov.w);
}

// ---------------- head conv layer (float4, tap-major weights) ----------------
__global__ void conv_head_kernel(const float4* __restrict__ in, float4* __restrict__ out,
                                 const float* __restrict__ hwt, const float* __restrict__ hb, int layer)
{
    int idx = blockIdx.x*256 + threadIdx.x;
    if (idx >= TOTAL/4) return;
    int c4 = idx % H4;
    int t  = idx / H4;
    int s  = t & (SEQ-1);
    int ch = c4*4;
    int head = ch / HDH;
    int cin  = ch % HDH;
    int d = c_head_dil[head][layer];
    int hl = head*3 + layer;
    float4 wj[4];
    #pragma unroll
    for (int j=0;j<4;j++) wj[j] = ((const float4*)(hwt + (hl*4 + j)*HDH))[cin>>2];
    float4 b4 = ((const float4*)hb)[(hl*HDH + cin)>>2];
    float acc[4] = {b4.x, b4.y, b4.z, b4.w};
    #pragma unroll
    for (int j=0;j<4;j++){
        int sp = s - (3-j)*d;
        if (sp >= 0){
            float4 xv = in[idx + (sp - s)*H4];
            acc[0] += wj[j].x*xv.x;
            acc[1] += wj[j].y*xv.y;
            acc[2] += wj[j].z*xv.z;
            acc[3] += wj[j].w*xv.w;
        }
    }
    float4 iv = in[idx];
    out[idx] = make_float4(iv.x+acc[0], iv.y+acc[1], iv.z+acc[2], iv.w+acc[3]);
}

// ---------------- hw mul (fp32 inplace + fp16 copy) ----------------
__global__ void hwmul_kernel(float4* __restrict__ a, const float* __restrict__ hw,
                             __half* __restrict__ outh)
{
    int idx = blockIdx.x*256 + threadIdx.x;
    if (idx >= TOTAL/4) return;
    int t = idx / H4, h = (idx % H4)*4/HDH;
    float g = hw[t*12 + h];
    float4 v = a[idx];
    float4 o = make_float4(v.x*g, v.y*g, v.z*g, v.w*g);
    a[idx] = o;
    st_h4(outh + (long)idx*4, o.x, o.y, o.z, o.w);
}

// ---------------- memory-head gate g and chunk means ----------------
__global__ void memg_kernel(const float* __restrict__ xg, const float* __restrict__ gw,
                            const float* __restrict__ gb, float* __restrict__ g)
{
    int t = blockIdx.x;
    int warp = threadIdx.x >> 5, lane = threadIdx.x & 31;
    const float* xr = xg + (long)t*HDIM + (6+warp)*HDH;
    const float* w  = gw + warp*HDH;
    float acc = 0.f;
    for (int c=lane;c<HDH;c+=32) acc += xr[c]*w[c];
    for (int o=16;o;o>>=1) acc += __shfl_down_sync(~0u,acc,o);
    if (lane==0) g[t*NMH+warp] = 1.f/(1.f+expf(-(acc + gb[warp])));
}

__global__ void ga_kernel(const float* __restrict__ g, float* __restrict__ ga)
{
    int e = blockIdx.x*256 + threadIdx.x;
    if (e >= 4*32*NMH) return;
    int n = e % NMH, ch = (e/NMH) % 32, b = e/(NMH*32);
    int base = (b*SEQ + ch*64)*NMH + n;
    float s = 0.f;
    for (int i=0;i<64;i++) s += g[base + i*NMH];
    ga[e] = s*(1.f/64.f);
}

// ---------------- chunked fast-weight scan: grid (16,8), 128 threads ----------------
#define SQS 100
__global__ void scan_kernel(const float* __restrict__ q, const float* __restrict__ kk,
                            const float* __restrict__ v, const float* __restrict__ g,
                            const float* __restrict__ ga, __half* __restrict__ reads)
{
    extern __shared__ float smx[];
    float* sM = smx;               // 96*16
    float* sQ = sM + 96*16;        // 64*SQS
    float* sK = sQ + 64*SQS;       // 64*SQS
    float* sV = sK + 64*SQS;       // 64*16
    float4* sM4 = (float4*)sM;
    float4* sV4 = (float4*)sV;
    int bn = blockIdx.x;
    int b = bn >> 2, n = bn & 3;
    int m0 = blockIdx.y * 16;
    int tid = threadIdx.x;
    const int dd0 = (tid >> 2) * 3;
    const int mg  = tid & 3;

    for (int i=tid;i<96*16;i+=128) sM[i]=0.f;
    __syncthreads();
    for (int ch=0; ch<32; ch++){
        int tok0 = b*SEQ + ch*64;
        #pragma unroll
        for (int it=0; it<12; it++){
            int i = tid + it*128;
            int s = i/24, cc = i%24;
            long base = (long)(tok0+s)*(NMH*HDH) + n*HDH;
            float gv = g[(tok0+s)*NMH + n];
            float4 qv = ((const float4*)(q + base))[cc];
            float4 kv = ((const float4*)(kk + base))[cc];
            ((float4*)(sQ + s*SQS))[cc] = qv;
            ((float4*)(sK + s*SQS))[cc] = make_float4(kv.x*gv, kv.y*gv, kv.z*gv, kv.w*gv);
        }
        #pragma unroll
        for (int it=0; it<2; it++){
            int i = tid + it*128;
            int s = i >> 2, mm = i & 3;
            sV4[i] = ((const float4*)(v + (long)(tok0+s)*(NMH*MDH) + n*MDH + m0))[mm];
        }
        __syncthreads();
        #pragma unroll
        for (int it=0; it<2; it++){
            int item = tid + it*128;
            int s = item >> 2, mgg = item & 3;
            const float* qs = sQ + s*SQS;
            float4 acc = make_float4(0.f,0.f,0.f,0.f);
            #pragma unroll 4
            for (int dd=0; dd<96; dd++){
                float qv = qs[dd];
                float4 mv = sM4[dd*4 + mgg];
                acc.x += qv*mv.x; acc.y += qv*mv.y; acc.z += qv*mv.z; acc.w += qv*mv.w;
            }
            st_h4(reads + (long)(tok0+s)*(NMH*MDH) + n*MDH + m0 + mgg*4,
                  acc.x, acc.y, acc.z, acc.w);
        }
        __syncthreads();
        float gav = ga[(b*32+ch)*NMH + n];
        float om = 1.f - gav;
        float4 a0 = sM4[(dd0+0)*4+mg];
        float4 a1 = sM4[(dd0+1)*4+mg];
        float4 a2 = sM4[(dd0+2)*4+mg];
        a0.x*=om; a0.y*=om; a0.z*=om; a0.w*=om;
        a1.x*=om; a1.y*=om; a1.z*=om; a1.w*=om;
        a2.x*=om; a2.y*=om; a2.z*=om; a2.w*=om;
        __syncthreads();
        #pragma unroll 2
        for (int s=0;s<64;s++){
            const float* ks = sK + s*SQS + dd0;
            float k0 = ks[0], k1 = ks[1], k2 = ks[2];
            float4 vv = sV4[s*4+mg];
            a0.x += k0*vv.x; a0.y += k0*vv.y; a0.z += k0*vv.z; a0.w += k0*vv.w;
            a1.x += k1*vv.x; a1.y += k1*vv.y; a1.z += k1*vv.z; a1.w += k1*vv.w;
            a2.x += k2*vv.x; a2.y += k2*vv.y; a2.z += k2*vv.z; a2.w += k2*vv.w;
        }
        sM4[(dd0+0)*4+mg] = a0;
        sM4[(dd0+1)*4+mg] = a1;
        sM4[(dd0+2)*4+mg] = a2;
        __syncthreads();
    }
}
#define SCAN_SMEM ((96*16 + 2*64*SQS + 64*16)*4)   // 59392

// ---------------- fp16 tensor-core GEMM (m16n8k16, cp.async 3-stage, K-chunk 16) ----------------
// C[M,N] = A[M,K](half, row-major) @ B[N,K](half, row-major)^T, fp32 accumulate. ldb = K-stride.
// EPI: 0 plain(+bias), 1 resid Cf=E+gate[r]*(acc+bias), 2 mulsig out=E*sig(acc+bias),
//      3 Cf+=acc, 4 GLU pairs out[r][cN/2]=acc_even*sig(acc_odd) (ldc=N/2)
// OM: 0 = fp32 out only (Cf), 1 = half out only (Ch), 2 = both.
#define ASTH 24
#define BSTH 24
#define SFTH (128*ASTH + 128*BSTH)   // 6144 halves per stage
template<bool BIAS, int EPI, int OM>
__global__ __launch_bounds__(256) void hgemm(
    const __half* __restrict__ A, const __half* __restrict__ B,
    const float* __restrict__ bias, float* __restrict__ Cf, __half* __restrict__ Ch,
    const float* __restrict__ E, const float* __restrict__ gate,
    int M, int N, int K, int lda, int ldb, int ldc,
    long zA, long zB, long zC)
{
    __shared__ __align__(16) __half smh[3*SFTH];

    A += (long)blockIdx.z * zA;
    B += (long)blockIdx.z * zB;
    if (OM != 1) Cf += (long)blockIdx.z * zC;
    if (OM != 0) Ch += (long)blockIdx.z * zC;
    if (EPI == 1 || EPI == 2) E += (long)blockIdx.z * zC;

    const int tid  = threadIdx.x;
    const int lane = tid & 31;
    const int wid  = tid >> 5;
    const int wm   = (wid >> 2) * 64;
    const int wn   = (wid & 3) * 32;
    const int qr   = lane >> 2;
    const int qc   = lane & 3;

    const int row0 = blockIdx.y * 128;
    const int col0 = blockIdx.x * 128;

    const int lr   = tid >> 1;
    const int lsg  = (tid & 1) * 8;
    const bool bok = (col0 + lr) < N;

    float acc[4][4][4];
    #pragma unroll
    for (int i=0;i<4;i++)
        #pragma unroll
        for (int j=0;j<4;j++)
            #pragma unroll
            for (int e=0;e<4;e++) acc[i][j][e]=0.f;

    const int nt = K >> 4;

    auto issue = [&](int t){
        __half* as = smh + (t%3)*SFTH;
        __half* bs = as + 128*ASTH;
        const int kb = t*16;
        cpasync16(smem_u32(as + lr*ASTH + lsg), A + (long)(row0 + lr)*lda + kb + lsg);
        if (bok)
            cpasync16(smem_u32(bs + lr*BSTH + lsg), B + (long)(col0 + lr)*ldb + kb + lsg);
        else
            cpasync16z(smem_u32(bs + lr*BSTH + lsg), B);
        asm volatile("cp.async.commit_group;" ::: "memory");
    };

    issue(0);
    if (nt > 1) issue(1);

    for (int t=0; t<nt; t++){
        if (t+1 < nt) asm volatile("cp.async.wait_group 1;" ::: "memory");
        else          asm volatile("cp.async.wait_group 0;" ::: "memory");
        __syncthreads();
        if (t+2 < nt) issue(t+2);
        const uint32_t* as32 = (const uint32_t*)(smh + (t%3)*SFTH);
        const uint32_t* bs32 = as32 + 128*(ASTH/2);
        uint32_t af[4][4], bf[4][2];
        #pragma unroll
        for (int i=0;i<4;i++){
            int rb = (wm + i*16 + qr)*(ASTH/2) + qc;
            af[i][0] = as32[rb];
            af[i][1] = as32[rb + 8*(ASTH/2)];
            af[i][2] = as32[rb + 4];
            af[i][3] = as32[rb + 8*(ASTH/2) + 4];
        }
        #pragma unroll
        for (int j=0;j<4;j++){
            int cb = (wn + j*8 + qr)*(BSTH/2) + qc;
            bf[j][0] = bs32[cb];
            bf[j][1] = bs32[cb + 4];
        }
        #pragma unroll
        for (int i=0;i<4;i++)
            #pragma unroll
            for (int j=0;j<4;j++){
                asm volatile(
                    "mma.sync.aligned.m16n8k16.row.col.f32.f16.f16.f32 "
                    "{%0,%1,%2,%3},{%4,%5,%6,%7},{%8,%9},{%0,%1,%2,%3};"
                    : "+f"(acc[i][j][0]), "+f"(acc[i][j][1]),
                      "+f"(acc[i][j][2]), "+f"(acc[i][j][3])
                    : "r"(af[i][0]), "r"(af[i][1]), "r"(af[i][2]), "r"(af[i][3]),
                      "r"(bf[j][0]), "r"(bf[j][1]));
            }
    }

    // epilogue
    #pragma unroll
    for (int i=0;i<4;i++){
        int r0 = row0 + wm + i*16 + qr;
        float gg0 = 0.f, gg1 = 0.f;
        if (EPI == 1){ gg0 = gate[r0]; gg1 = gate[r0+8]; }
        #pragma unroll
        for (int j=0;j<4;j++){
            int cN = col0 + wn + j*8 + qc*2;
            if (cN < N){
                float bv0 = BIAS ? bias[cN]   : 0.f;
                float bv1 = BIAS ? bias[cN+1] : 0.f;
                float v0 = acc[i][j][0] + bv0;
                float v1 = acc[i][j][1] + bv1;
                float v2 = acc[i][j][2] + bv0;
                float v3 = acc[i][j][3] + bv1;
                if (EPI == 4){
                    long p0 = (long)r0*ldc + (cN>>1);
                    long p1 = (long)(r0+8)*ldc + (cN>>1);
                    float g0 = v0*sigmoidf_(v1);
                    float g1 = v2*sigmoidf_(v3);
                    if (OM != 1){ Cf[p0] = g0; Cf[p1] = g1; }
                    if (OM != 0){ Ch[p0] = __float2half_rn(g0); Ch[p1] = __float2half_rn(g1); }
                } else {
                    long o00 = (long)r0*ldc + cN;
                    long o10 = (long)(r0+8)*ldc + cN;
                    if (EPI == 1){
                        v0 = E[o00]   + gg0*v0;
                        v1 = E[o00+1] + gg0*v1;
                        v2 = E[o10]   + gg1*v2;
                        v3 = E[o10+1] + gg1*v3;
                    } else if (EPI == 2){
                        v0 = E[o00]  *sigmoidf_(v0);
                        v1 = E[o00+1]*sigmoidf_(v1);
                        v2 = E[o10]  *sigmoidf_(v2);
                        v3 = E[o10+1]*sigmoidf_(v3);
                    } else if (EPI == 3){
                        v0 += Cf[o00]; v1 += Cf[o00+1]; v2 += Cf[o10]; v3 += Cf[o10+1];
                    }
                    if (OM != 1){
                        Cf[o00] = v0; Cf[o00+1] = v1;
                        Cf[o10] = v2; Cf[o10+1] = v3;
                    }
                    if (OM != 0){
                        __half2 h0 = __floats2half2_rn(v0, v1);
                        __half2 h1 = __floats2half2_rn(v2, v3);
                        *(__half2*)(Ch + o00) = h0;
                        *(__half2*)(Ch + o10) = h1;
                    }
                }
            }
        }
    }
}

// ---------------- host ----------------
extern "C" void kernel_launch(void* const* d_in, const int* in_sizes, int n_in,
                              void* d_out, int out_size)
{
    const float* x          = (const float*)d_in[0];
    const float* norm1_w    = (const float*)d_in[1];
    const float* norm2_w    = (const float*)d_in[2];
    const float* norm3_w    = (const float*)d_in[3];
    const float* cs_w       = (const float*)d_in[4];
    const float* cs_b       = (const float*)d_in[5];
    const float* cs_proj_w  = (const float*)d_in[6];
    const float* cs_proj_b  = (const float*)d_in[7];
    const float* gate_proj_w= (const float*)d_in[8];
    const float* router_w   = (const float*)d_in[9];
    const float* router_b   = (const float*)d_in[10];
    const float* head_w     = (const float*)d_in[11];
    const float* head_b     = (const float*)d_in[12];
    const float* mem_q      = (const float*)d_in[13];
    const float* mem_k      = (const float*)d_in[14];
    const float* mem_v      = (const float*)d_in[15];
    const float* mem_gw     = (const float*)d_in[16];
    const float* mem_gb     = (const float*)d_in[17];
    const float* mem_out    = (const float*)d_in[18];
    const float* mixgate_w  = (const float*)d_in[19];
    const float* mixgate_b  = (const float*)d_in[20];
    const float* mixing_w   = (const float*)d_in[21];
    const float* mixing_b   = (const float*)d_in[22];
    const float* ffn_in_w   = (const float*)d_in[23];
    const float* ffn_out_w  = (const float*)d_in[24];
    const float* cg_w       = (const float*)d_in[25];
    const float* cg_b       = (const float*)d_in[26];
    const float* sg_w       = (const float*)d_in[27];
    const float* sg_b       = (const float*)d_in[28];
    const float* fg_w       = (const float*)d_in[29];
    const float* fg_b       = (const float*)d_in[30];

    float *X,*A,*Bb,*C,*Q,*Kb,*V,*G,*GA,*GATE,*HW,*CSWT,*HDWT;
    __half *H1,*H2,*GLUH,*RH,*WPGP,*WPFI,*WCS,*WMG,*WMX,*WFO,*WMQ,*WMK,*WMV,*WMO;
    cudaGetSymbolAddress((void**)&X,  g_x);
    cudaGetSymbolAddress((void**)&A,  g_a);
    cudaGetSymbolAddress((void**)&Bb, g_b);
    cudaGetSymbolAddress((void**)&C,  g_c);
    cudaGetSymbolAddress((void**)&Q,  g_q);
    cudaGetSymbolAddress((void**)&Kb, g_k);
    cudaGetSymbolAddress((void**)&V,  g_v);
    cudaGetSymbolAddress((void**)&G,  g_g);
    cudaGetSymbolAddress((void**)&GA, g_ga);
    cudaGetSymbolAddress((void**)&GATE,g_gate);
    cudaGetSymbolAddress((void**)&HW, g_hw);
    cudaGetSymbolAddress((void**)&CSWT, g_cs_wt);
    cudaGetSymbolAddress((void**)&HDWT, g_hd_wt);
    cudaGetSymbolAddress((void**)&H1, g_h1);
    cudaGetSymbolAddress((void**)&H2, g_h2);
    cudaGetSymbolAddress((void**)&GLUH, g_gluh);
    cudaGetSymbolAddress((void**)&RH, g_rh);
    cudaGetSymbolAddress((void**)&WPGP, g_wp_gp);
    cudaGetSymbolAddress((void**)&WPFI, g_wp_fi);
    cudaGetSymbolAddress((void**)&WCS, g_w_cs);
    cudaGetSymbolAddress((void**)&WMG, g_w_mg);
    cudaGetSymbolAddress((void**)&WMX, g_w_mx);
    cudaGetSymbolAddress((void**)&WFO, g_w_fo);
    cudaGetSymbolAddress((void**)&WMQ, g_w_mq);
    cudaGetSymbolAddress((void**)&WMK, g_w_mk);
    cudaGetSymbolAddress((void**)&WMV, g_w_mv);
    cudaGetSymbolAddress((void**)&WMO, g_w_mo);

    cudaFuncSetAttribute(scan_kernel, cudaFuncAttributeMaxDynamicSharedMemorySize, SCAN_SMEM);

    const int EB4 = TOTAL/4/256;   // 9216
    dim3 tb(32,8);

    // ===== weight preps: half [N][K] transposed (+pair-interleave for GLU) =====
    wtrans_h<true> <<<dim3(72,36,1),  tb>>>(gate_proj_w, WPGP, 1152, 2304);
    wtrans_h<true> <<<dim3(288,36,1), tb>>>(ffn_in_w,    WPFI, 1152, 9216);
    wtrans_h<false><<<dim3(36,36,1),  tb>>>(cs_proj_w,   WCS,  1152, 1152);
    wtrans_h<false><<<dim3(36,36,1),  tb>>>(mixgate_w,   WMG,  1152, 1152);
    wtrans_h<false><<<dim3(36,36,1),  tb>>>(mixing_w,    WMX,  1152, 1152);
    wtrans_h<false><<<dim3(36,144,1), tb>>>(ffn_out_w,   WFO,  4608, 1152);
    wtrans_h<false><<<dim3(3,3,4),    tb>>>(mem_q,       WMQ,  96, 96);
    wtrans_h<false><<<dim3(3,3,4),    tb>>>(mem_k,       WMK,  96, 96);
    wtrans_h<false><<<dim3(4,3,4),    tb>>>(mem_v,       WMV,  96, 128);
    wtrans_h<false><<<dim3(3,4,4),    tb>>>(mem_out,     WMO,  128, 96);
    wtrans_kernel<<<108,256>>>(cs_w, head_w, CSWT, HDWT);

    // ===== stage 1: conv stack =====
    rms_gate_kernel<<<NTOK,256>>>(x, norm1_w, cg_w, cg_b, A, H1, GATE);
    {
        const int dil[6] = {1,2,4,8,16,32};
        float* pin = A; float* pout = Bb;
        for (int i=0;i<6;i++){
            conv_cs_kernel<<<EB4,256>>>((const float4*)pin, (float4*)pout,
                CSWT + i*4*HDIM, (const float4*)(cs_b + i*HDIM), H1, dil[i], i==5);
            float* tmp = pin; pin = pout; pout = tmp;
        }
    }
    // X = x + gate*(H1@cs_proj + b)
    hgemm<true,1,0><<<dim3(9,64,1),256>>>(H1, WCS, cs_proj_b, X, nullptr, x, GATE,
        NTOK, HDIM, HDIM, HDIM, HDIM, HDIM, 0,0,0);

    // ===== stage 2: multi-head state =====
    rms_gate_kernel<<<NTOK,256>>>(X, norm2_w, sg_w, sg_b, nullptr, H1, GATE);
    router_kernel<<<NTOK,128>>>(H1, router_w, router_b, HW);
    // Bb(f32) + H2(h16) = glu(H1 @ gate_proj)
    hgemm<false,4,2><<<dim3(18,64,1),256>>>(H1, WPGP, nullptr, Bb, H2, nullptr, nullptr,
        NTOK, 2304, HDIM, HDIM, HDIM, HDIM, 0,0,0);
    memg_kernel<<<NTOK,128>>>(Bb, mem_gw, mem_gb, G);
    ga_kernel<<<2,256>>>(G, GA);
    hgemm<false,0,0><<<dim3(1,64,4),256>>>(H2 + 6*HDH, WMQ, nullptr, Q, nullptr, nullptr, nullptr,
        NTOK, HDH, HDH, HDIM, HDH, NMH*HDH, HDH, HDH*HDH, HDH);
    hgemm<false,0,0><<<dim3(1,64,4),256>>>(H2 + 6*HDH, WMK, nullptr, Kb, nullptr, nullptr, nullptr,
        NTOK, HDH, HDH, HDIM, HDH, NMH*HDH, HDH, HDH*HDH, HDH);
    hgemm<false,0,0><<<dim3(1,64,4),256>>>(H2 + 6*HDH, WMV, nullptr, V, nullptr, nullptr, nullptr,
        NTOK, MDH, HDH, HDIM, HDH, NMH*MDH, HDH, HDH*MDH, MDH);
    conv_head_kernel<<<EB4,256>>>((const float4*)Bb, (float4*)C, HDWT, head_b, 0);
    conv_head_kernel<<<EB4,256>>>((const float4*)C,  (float4*)A, HDWT, head_b, 1);
    conv_head_kernel<<<EB4,256>>>((const float4*)A,  (float4*)C, HDWT, head_b, 2);
    scan_kernel<<<dim3(16,8),128,SCAN_SMEM>>>(Q, Kb, V, G, GA, RH);
    // C[:, memheads] += RH @ mem_out
    hgemm<false,3,0><<<dim3(1,64,4),256>>>(RH, WMO, nullptr, C + 6*HDH, nullptr, nullptr, nullptr,
        NTOK, HDH, MDH, NMH*MDH, MDH, HDIM, MDH, MDH*HDH, HDH);
    hwmul_kernel<<<EB4,256>>>((float4*)C, HW, H1);
    // H2 = C * sigmoid(H1@mixgate + b)
    hgemm<true,2,1><<<dim3(9,64,1),256>>>(H1, WMG, mixgate_b, nullptr, H2, C, nullptr,
        NTOK, HDIM, HDIM, HDIM, HDIM, HDIM, 0,0,0);
    // X = X + gate*(H2@mixing + b)
    hgemm<true,1,0><<<dim3(9,64,1),256>>>(H2, WMX, mixing_b, X, nullptr, X, GATE,
        NTOK, HDIM, HDIM, HDIM, HDIM, HDIM, 0,0,0);

    // ===== stage 3: GLU FFN =====
    rms_gate_kernel<<<NTOK,256>>>(X, norm3_w, fg_w, fg_b, nullptr, H1, GATE);
    // GLUH = glu(H1 @ ffn_in)
    hgemm<false,4,1><<<dim3(72,64,1),256>>>(H1, WPFI, nullptr, nullptr, GLUH, nullptr, nullptr,
        NTOK, 9216, HDIM, HDIM, HDIM, INNERD, 0,0,0);
    // out = X + gate*(GLUH@ffn_out)
    hgemm<false,1,0><<<dim3(9,64,1),256>>>(GLUH, WFO, nullptr, (float*)d_out, nullptr, X, GATE,
        NTOK, HDIM, INNERD, INNERD, INNERD, HDIM, 0,0,0);

    (void)in_sizes; (void)n_in; (void)out_size;
}